// round 17
// baseline (speedup 1.0000x reference)
#include <cuda_runtime.h>
#include <math.h>

#define BB 32
#define CC 64
#define HH 128
#define WW 128
#define HW (HH*WW)
#define CHW (CC*HW)
#define NB 3
#define RH 8

#define TSX 32             // tile width
#define TSY 16             // tile height
#define HALO 6
#define TLX (TSX + 2*HALO) // 44
#define TLY (TSY + 2*HALO) // 28
#define TLP (TLX + 1)      // 45 float2 row stride -> conflict-free LDS.64

#define NRED 2048          // reduce strips (2 rows each)
#define NGB  64            // G-map blocks (placed FIRST in kA's grid)
#define NTILES 1024        // kC tiles
#define PF 4               // x channels prefetched into registers during conv
#define GRP 6              // apply-phase channel burst size

// scratch (device globals: no allocation allowed)
__device__ float2 g_am[BB*HW];        // interleaved (avg, max)
__device__ float  g_partA[NRED];
__device__ float  g_partM[NRED];
__device__ float  g_rw[BB*NB];
__device__ float  g_G[3*HW];          // xg/yg conv response per branch (pw-folded)
__device__ unsigned g_cnt = 0;        // router last-block counter (reset in-kernel)
// monotonic pipeline flags (never reset; epoch-counted)
__device__ unsigned g_fstrip[NRED];   // zero-init
__device__ unsigned g_fG = 0;
__device__ unsigned g_fR = 0;
__device__ unsigned g_tick = 0;

__device__ __forceinline__ unsigned ldacq(const unsigned* p) {
    unsigned v;
    asm volatile("ld.acquire.gpu.u32 %0, [%1];" : "=r"(v) : "l"(p) : "memory");
    return v;
}
__device__ __forceinline__ void stg_cs2(float* p, float2 v) {
    asm volatile("st.global.cs.v2.f32 [%0], {%1,%2};"
                 :: "l"(p), "f"(v.x), "f"(v.y) : "memory");
}

// ---------------------------------------------------------------------------
// Kernel A: blocks 0..63: G maps (first -> complete early). Blocks 64..2111:
// per-pixel channel reduce (avg,max), 1 px/thread, strip = 2 rows; sets a
// per-strip flag. Last strip block computes the router and sets g_fR.
// launch_dependents at ENTRY: kC launches once all kA blocks have started.
// ---------------------------------------------------------------------------
__global__ __launch_bounds__(256) void kA(
    const float* __restrict__ x,
    const float* __restrict__ dw0, const float* __restrict__ dw1,
    const float* __restrict__ dw2,
    const float* __restrict__ pw0w, const float* __restrict__ pw1w,
    const float* __restrict__ pw2w,
    const float* __restrict__ rw1, const float* __restrict__ rb1,
    const float* __restrict__ rw2, const float* __restrict__ rb2)
{
    asm volatile("griddepcontrol.launch_dependents;" ::: "memory");

    int blk = blockIdx.x;
    int tid = threadIdx.x;

    if (blk < NGB) {
        // ---- G-map unit ----
        int p = blk * 256 + tid;                     // 0..16383
        int gy = p >> 7, gx = p & 127;

        const float* dws[3] = {dw0, dw1, dw2};
        const float* pws[3] = {pw0w, pw1w, pw2w};
        const int ks[3]  = {3, 7, 7};
        const int dil[3] = {1, 1, 2};

        #pragma unroll
        for (int i = 0; i < 3; ++i) {
            int k = ks[i], d = dil[i], r = k / 2;
            float p2 = pws[i][2], p3 = pws[i][3];
            const float* w2 = dws[i] + 2 * k * k;
            const float* w3 = dws[i] + 3 * k * k;
            float acc = 0.0f;
            for (int dy = 0; dy < k; ++dy) {
                int yy = gy + d * (dy - r);
                if ((unsigned)yy >= (unsigned)HH) continue;
                float yv = -1.0f + (float)yy * (2.0f / 127.0f);
                for (int dx = 0; dx < k; ++dx) {
                    int xx = gx + d * (dx - r);
                    if ((unsigned)xx >= (unsigned)WW) continue;
                    float xv = -1.0f + (float)xx * (2.0f / 127.0f);
                    int t = dy * k + dx;
                    acc += p2 * w2[t] * xv + p3 * w3[t] * yv;
                }
            }
            g_G[i * HW + p] = acc;
        }
        __threadfence();
        __syncthreads();
        if (tid == 0) atomicAdd(&g_fG, 1u);
        return;
    }

    // ---- channel reduce: strip = 2 rows of one image ----
    int strip = blk - NGB;
    int b = strip >> 6;
    int sp = ((strip & 63) << 8) + tid;
    const float* p = x + (size_t)b * CHW + sp;

    float s = 0.0f, m = -INFINITY;
    #pragma unroll 16
    for (int c = 0; c < CC; ++c) {
        float v = p[c * HW];
        s += v;
        m = fmaxf(m, v);
    }
    float av = s * (1.0f / 64.0f);
    g_am[b * HW + sp] = make_float2(av, m);
    __threadfence();   // order this thread's g_am store before the strip flag

    // deterministic block reduction of (sum of avg, sum of max)
    float ra = av, rm = m;
    #pragma unroll
    for (int o = 16; o; o >>= 1) {
        ra += __shfl_down_sync(0xffffffffu, ra, o);
        rm += __shfl_down_sync(0xffffffffu, rm, o);
    }
    __shared__ float sA[8], sM[8];
    int w = tid >> 5, l = tid & 31;
    if (l == 0) { sA[w] = ra; sM[w] = rm; }
    __syncthreads();

    __shared__ bool amLast;
    if (tid == 0) {
        float ta = 0.f, tm = 0.f;
        #pragma unroll
        for (int i = 0; i < 8; ++i) { ta += sA[i]; tm += sM[i]; }
        g_partA[strip] = ta;
        g_partM[strip] = tm;
        __threadfence();
        atomicAdd(&g_fstrip[strip], 1u);            // publish strip
        amLast = (atomicAdd(&g_cnt, 1u) == NRED - 1);
    }
    __syncthreads();
    if (!amLast) return;

    if (tid == 0) g_cnt = 0;   // reset for next graph replay

    // ---- router, by the designated last block ----
    int batch = tid >> 3;
    int j = tid & 7;
    float a = 0.f, mm = 0.f;
    #pragma unroll
    for (int i = 0; i < 8; ++i) {
        int idx = batch * 64 + j * 8 + i;
        a  += g_partA[idx];
        mm += g_partM[idx];
    }
    #pragma unroll
    for (int o = 4; o; o >>= 1) {
        a  += __shfl_down_sync(0xffffffffu, a,  o, 8);
        mm += __shfl_down_sync(0xffffffffu, mm, o, 8);
    }
    __shared__ float bA[32], bM[32];
    if (j == 0) { bA[batch] = a; bM[batch] = mm; }
    __syncthreads();

    if (tid < 32) {
        float p0 = bA[tid] * (1.0f / (float)HW);
        float p1 = bM[tid] * (1.0f / (float)HW);
        // pooled xg, yg are exactly 0 (symmetric linspace)
        float hid[RH];
        #pragma unroll
        for (int jj = 0; jj < RH; ++jj) {
            float h = rw1[jj * 4 + 0] * p0 + rw1[jj * 4 + 1] * p1 + rb1[jj];
            hid[jj] = fmaxf(h, 0.0f);
        }
        float lg[NB];
        float mx = -INFINITY;
        #pragma unroll
        for (int i = 0; i < NB; ++i) {
            float ss = rb2[i];
            #pragma unroll
            for (int jj = 0; jj < RH; ++jj) ss += rw2[i * RH + jj] * hid[jj];
            lg[i] = ss;
            mx = fmaxf(mx, ss);
        }
        float den = 0.0f;
        #pragma unroll
        for (int i = 0; i < NB; ++i) { lg[i] = expf(lg[i] - mx); den += lg[i]; }
        float inv = 1.0f / den;
        #pragma unroll
        for (int i = 0; i < NB; ++i) g_rw[tid * NB + i] = lg[i] * inv;
        __threadfence();
    }
    __syncthreads();
    if (tid == 0) atomicAdd(&g_fR, 1u);             // publish router
}

// ---------------------------------------------------------------------------
// Kernel C: 32x16 tile, 2 outputs/thread. PDL-launched; waits on per-strip
// data flags (not full kA). Conv uses per-branch accumulators so the router
// value is only needed AFTER the conv (waited then).
// ---------------------------------------------------------------------------
#define DOT2(acc, v, w) \
    acc = fmaf((v).x, (w).x, fmaf((v).y, (w).y, (acc)))

__global__ __launch_bounds__(256, 4) void kC(
    const float* __restrict__ x,
    const float* __restrict__ dw0, const float* __restrict__ dw1, const float* __restrict__ dw2,
    const float* __restrict__ pw0w, const float* __restrict__ pw0b,
    const float* __restrict__ pw1w, const float* __restrict__ pw1b,
    const float* __restrict__ pw2w, const float* __restrict__ pw2b,
    const float* __restrict__ traw,
    float* __restrict__ outY, float* __restrict__ outSA)
{
    __shared__ float2 s2[TLY][TLP];
    __shared__ float2 w0s[9], w1s[49], w2s[49];
    __shared__ float2 saS[TSY][17];   // [16 rows][16 pairs + pad]
    __shared__ float shrw[3];
    __shared__ float shmisc[5];       // invT, pwb0, pwb1, pwb2
    __shared__ unsigned shE;

    const int b  = blockIdx.z;
    const int x0 = blockIdx.x * TSX;
    const int y0 = blockIdx.y * TSY;
    const int tid = threadIdx.x;

    // ---- prologue: everything independent of kA ----
    const int py = tid >> 4;          // 0..15 (row)
    const int xp = tid & 15;          // 0..15 (pair)
    const int base = (y0 + py) * WW + x0 + xp * 2;
    const float* xb = x + (size_t)b * CHW + base;
    float* yb = outY + (size_t)b * CHW + base;

    float2 px[PF];
    #pragma unroll
    for (int i = 0; i < PF; ++i)
        px[i] = *(const float2*)(xb + i * HW);

    if (tid == 0) {
        float T = log1pf(expf(traw[0])) + 1e-6f;
        shmisc[0] = 1.0f / T;
        shmisc[1] = pw0b[0];
        shmisc[2] = pw1b[0];
        shmisc[3] = pw2b[0];
        shE = atomicAdd(&g_tick, 1u) / NTILES + 1u;  // epoch
    }
    // pointwise-only weight fold (router applied post-conv)
    if (tid < 9) {
        w0s[tid] = make_float2(pw0w[0] * dw0[0 * 9 + tid],
                               pw0w[1] * dw0[1 * 9 + tid]);
    } else if (tid < 58) {
        int i = tid - 9;
        w1s[i] = make_float2(pw1w[0] * dw1[0 * 49 + i],
                             pw1w[1] * dw1[1 * 49 + i]);
    } else if (tid < 107) {
        int i = tid - 58;
        w2s[i] = make_float2(pw2w[0] * dw2[0 * 49 + i],
                             pw2w[1] * dw2[1 * 49 + i]);
    }
    __syncthreads();
    const unsigned E = shE;

    // ---- wait for the strips this tile needs (+ G maps) ----
    {
        int rlo = (y0 >= HALO) ? (y0 - HALO) : 0;
        int rhi = y0 + TSY - 1 + HALO; if (rhi > 127) rhi = 127;
        int slo = rlo >> 1, shi = rhi >> 1;
        int ns = shi - slo + 1;                      // <= 14
        if (tid < ns) {
            const unsigned* f = &g_fstrip[b * 64 + slo + tid];
            while (ldacq(f) < E) { }
        } else if (tid == 32) {
            while (ldacq(&g_fG) < E * NGB) { }
        }
    }
    __threadfence();
    __syncthreads();

    // ---- load (avg,max) tile with zero halo padding ----
    const float2* am = g_am + b * HW;
    for (int i = tid; i < TLY * TLX; i += 256) {
        int ly = i / TLX, lx = i % TLX;
        int gy = y0 - HALO + ly, gx = x0 - HALO + lx;
        float2 v = make_float2(0.0f, 0.0f);
        if ((unsigned)gy < (unsigned)HH && (unsigned)gx < (unsigned)WW)
            v = am[gy * WW + gx];
        s2[ly][lx] = v;
    }

    // conv mapping: lane -> row (conflict-free), 16 x-pairs
    const int oy = tid & 15;
    const int gx8 = tid >> 4;
    const int ox = gx8 * 2;
    const int cy = oy + HALO;
    const int cx = ox + HALO;

    // G map loads (pw-folded, per branch)
    const int pix = (y0 + oy) * WW + x0 + ox;
    float G0[2], G1[2], G2[2];
    #pragma unroll
    for (int j = 0; j < 2; ++j) {
        G0[j] = g_G[0 * HW + pix + j];
        G1[j] = g_G[1 * HW + pix + j];
        G2[j] = g_G[2 * HW + pix + j];
    }

    __syncthreads();

    // per-branch accumulators (router applied after conv)
    float s00 = 0.f, s01 = 0.f;   // branch 0, px0/px1
    float s10 = 0.f, s11 = 0.f;   // branch 1
    float s20 = 0.f, s21 = 0.f;   // branch 2

    // branch 0: k=3, d=1
    #pragma unroll
    for (int dy = 0; dy < 3; ++dy) {
        const float2* row = s2[cy + dy - 1];
        float2 c[4];
        #pragma unroll
        for (int j = 0; j < 4; ++j) c[j] = row[cx - 1 + j];
        #pragma unroll
        for (int dx = 0; dx < 3; ++dx) {
            float2 w = w0s[dy * 3 + dx];
            DOT2(s00, c[dx + 0], w);
            DOT2(s01, c[dx + 1], w);
        }
    }

    // branch 1: k=7, d=1
    #pragma unroll
    for (int dy = 0; dy < 7; ++dy) {
        const float2* row = s2[cy + dy - 3];
        float2 c[8];
        #pragma unroll
        for (int j = 0; j < 8; ++j) c[j] = row[cx - 3 + j];
        #pragma unroll
        for (int dx = 0; dx < 7; ++dx) {
            float2 w = w1s[dy * 7 + dx];
            DOT2(s10, c[dx + 0], w);
            DOT2(s11, c[dx + 1], w);
        }
    }

    // branch 2: k=7, d=2
    #pragma unroll
    for (int ty = 0; ty < 7; ++ty) {
        const float2* row = s2[cy + 2 * (ty - 3)];
        float2 c[14];
        #pragma unroll
        for (int j = 0; j < 14; ++j) c[j] = row[cx - 6 + j];
        #pragma unroll
        for (int tx = 0; tx < 7; ++tx) {
            float2 w = w2s[ty * 7 + tx];
            DOT2(s20, c[2 * tx + 0], w);
            DOT2(s21, c[2 * tx + 1], w);
        }
    }

    // ---- wait for router, then combine ----
    if (tid == 0) {
        while (ldacq(&g_fR) < E) { }
        __threadfence();
        shrw[0] = g_rw[b * 3 + 0];
        shrw[1] = g_rw[b * 3 + 1];
        shrw[2] = g_rw[b * 3 + 2];
    }
    __syncthreads();
    const float r0 = shrw[0], r1 = shrw[1], r2 = shrw[2];
    const float invT = shmisc[0];
    const float b0v = shmisc[1], b1v = shmisc[2], b2v = shmisc[3];

    float f0 = r0 * (s00 + G0[0] + b0v) + r1 * (s10 + G1[0] + b1v)
             + r2 * (s20 + G2[0] + b2v);
    float f1 = r0 * (s01 + G0[1] + b0v) + r1 * (s11 + G1[1] + b1v)
             + r2 * (s21 + G2[1] + b2v);

    float2 sa;
    sa.x = 1.0f / (1.0f + __expf(-f0 * invT));
    sa.y = 1.0f / (1.0f + __expf(-f1 * invT));
    saS[oy][gx8] = sa;

    __syncthreads();

    // ---- apply phase ----
    float2 sv = saS[py][xp];
    *(float2*)(outSA + b * HW + base) = sv;

    #pragma unroll
    for (int i = 0; i < PF; ++i) {
        float2 v = px[i];
        v.x *= sv.x; v.y *= sv.y;
        stg_cs2(yb + i * HW, v);
    }
    #pragma unroll
    for (int g = 0; g < (CC - PF) / GRP; ++g) {
        const int c0 = PF + g * GRP;
        float2 v[GRP];
        #pragma unroll
        for (int k = 0; k < GRP; ++k)
            v[k] = *(const float2*)(xb + (c0 + k) * HW);
        #pragma unroll
        for (int k = 0; k < GRP; ++k) {
            v[k].x *= sv.x; v[k].y *= sv.y;
            stg_cs2(yb + (c0 + k) * HW, v[k]);
        }
    }
}

// ---------------------------------------------------------------------------
extern "C" void kernel_launch(void* const* d_in, const int* in_sizes, int n_in,
                              void* d_out, int out_size) {
    const float* x    = (const float*)d_in[0];
    const float* dw0  = (const float*)d_in[1];
    const float* dw1  = (const float*)d_in[2];
    const float* dw2  = (const float*)d_in[3];
    const float* pw0w = (const float*)d_in[4];
    const float* pw0b = (const float*)d_in[5];
    const float* pw1w = (const float*)d_in[6];
    const float* pw1b = (const float*)d_in[7];
    const float* pw2w = (const float*)d_in[8];
    const float* pw2b = (const float*)d_in[9];
    const float* rw1  = (const float*)d_in[10];
    const float* rb1  = (const float*)d_in[11];
    const float* rw2  = (const float*)d_in[12];
    const float* rb2  = (const float*)d_in[13];
    const float* traw = (const float*)d_in[14];

    float* outY  = (float*)d_out;
    float* outSA = (float*)d_out + (size_t)BB * CHW;

    kA<<<NGB + NRED, 256>>>(x, dw0, dw1, dw2, pw0w, pw1w, pw2w,
                            rw1, rb1, rw2, rb2);

    // kC via PDL: launches once all kA blocks have started; data sync via flags
    cudaLaunchConfig_t cfg = {};
    cfg.gridDim  = dim3(WW / TSX, HH / TSY, BB);
    cfg.blockDim = dim3(256, 1, 1);
    cfg.dynamicSmemBytes = 0;
    cfg.stream = 0;
    cudaLaunchAttribute attrs[1];
    attrs[0].id = cudaLaunchAttributeProgrammaticStreamSerialization;
    attrs[0].val.programmaticStreamSerializationAllowed = 1;
    cfg.attrs = attrs;
    cfg.numAttrs = 1;
    cudaLaunchKernelEx(&cfg, kC, x, dw0, dw1, dw2, pw0w, pw0b, pw1w, pw1b,
                       pw2w, pw2b, traw, outY, outSA);
}